// round 3
// baseline (speedup 1.0000x reference)
#include <cuda_runtime.h>
#include <math.h>

typedef unsigned long long ull;

#define FULLMASK 0xFFFFFFFFu
#define FEAT 192
#define NPROXY 64
#define NDIM 64
#define MAXN 50000
#define MAXR 512
#define TTILE 64
#define FUSE_THREADS 512
#define PITCH 66

// ---------------- static scratch (no allocation allowed) ----------------
static __device__ float g_out[MAXN * FEAT];     // concat outputs [N,192]
static __device__ float g_reln[MAXR * NDIM];    // normalized rel_emb rows
static __device__ float g_attrel[2 * MAXR];     // per-(layer,rel) attention scalar
static __device__ float g_pinv[NPROXY];         // 1/||proxy_row||

// ---------------- helpers ----------------
__device__ __forceinline__ ull ffma2(ull a, ull b, ull c) {
    ull d;
    asm("fma.rn.f32x2 %0, %1, %2, %3;" : "=l"(d) : "l"(a), "l"(b), "l"(c));
    return d;
}
__device__ __forceinline__ ull pack2(float lo, float hi) {
    ull r; asm("mov.b64 %0, {%1, %2};" : "=l"(r) : "f"(lo), "f"(hi)); return r;
}
__device__ __forceinline__ void unpack2(ull v, float& lo, float& hi) {
    asm("mov.b64 {%0, %1}, %2;" : "=f"(lo), "=f"(hi) : "l"(v));
}
__device__ __forceinline__ float warpSum(float v) {
    #pragma unroll
    for (int o = 16; o; o >>= 1) v += __shfl_xor_sync(FULLMASK, v, o);
    return v;
}
__device__ __forceinline__ float warpMax(float v) {
    #pragma unroll
    for (int o = 16; o; o >>= 1) v = fmaxf(v, __shfl_xor_sync(FULLMASK, v, o));
    return v;
}
__device__ __forceinline__ float sigmoidf_(float x) { return 1.f / (1.f + expf(-x)); }

// ---------------- prep: normalize rel rows + per-layer attention scalars ----------------
__global__ void prep_rel_kernel(const float* __restrict__ rel_emb,
                                const float* __restrict__ ak, int R, int L)
{
    __shared__ float red[2];
    int r = blockIdx.x, t = threadIdx.x;     // 64 threads
    float v = rel_emb[r * NDIM + t];
    float ss = warpSum(v * v);
    int w = t >> 5, ln = t & 31;
    if (ln == 0) red[w] = ss;
    __syncthreads();
    float inv = 1.f / fmaxf(sqrtf(red[0] + red[1]), 1e-12f);
    float vn = v * inv;
    g_reln[r * NDIM + t] = vn;
    for (int l = 0; l < L; l++) {
        __syncthreads();
        float a = warpSum(vn * ak[l * NDIM + t]);
        if (ln == 0) red[w] = a;
        __syncthreads();
        if (t == 0) g_attrel[l * R + r] = red[0] + red[1];
    }
}

// ---------------- prep: proxy row inverse norms ----------------
__global__ void prep_proxy_kernel(const float* __restrict__ proxy)
{
    __shared__ float red[6];
    int j = blockIdx.x, t = threadIdx.x;     // 192 threads
    float v = proxy[j * FEAT + t];
    float s = warpSum(v * v);
    if ((t & 31) == 0) red[t >> 5] = s;
    __syncthreads();
    if (t == 0) {
        float tot = red[0] + red[1] + red[2] + red[3] + red[4] + red[5];
        g_pinv[j] = 1.f / fmaxf(sqrtf(tot), 1e-12f);
    }
}

// ---------------- tanh(features) -> outputs[:, 0:64] ----------------
__global__ void tanh_kernel(const float* __restrict__ feat, int N)
{
    int i = blockIdx.x * blockDim.x + threadIdx.x;
    if (i < N * NDIM) {
        int n = i >> 6, d = i & 63;
        g_out[n * FEAT + d] = tanhf(feat[i]);
    }
}

// ---------------- one GNN layer: warp per node, deg contiguous edges ----------------
__global__ __launch_bounds__(256) void layer_kernel(
    const int* __restrict__ src, const int* __restrict__ rid,
    int l, int col_in, int col_out, int N, int deg, int R)
{
    int lane = threadIdx.x & 31;
    int node = (blockIdx.x << 3) + (threadIdx.x >> 5);
    if (node >= N) return;
    const float* __restrict__ attrel = g_attrel + l * R;
    int e0 = node * deg;
    int msrc = 0, mrid = 0; float matt = -3.0e38f;
    if (lane < deg) {
        msrc = src[e0 + lane];
        mrid = rid[e0 + lane];
        matt = attrel[mrid];
    }
    float m = warpMax(matt);
    float ex = (lane < deg) ? expf(matt - m) : 0.f;
    float s = warpSum(ex);
    float w = ex / s;
    int d2 = lane * 2;
    float ax = 0.f, ay = 0.f;
    for (int e = 0; e < deg; e++) {
        int   se = __shfl_sync(FULLMASK, msrc, e);
        int   re = __shfl_sync(FULLMASK, mrid, e);
        float we = __shfl_sync(FULLMASK, w, e);
        float2 h = *(const float2*)(g_out + se * FEAT + col_in + d2);
        float2 r = *(const float2*)(g_reln + re * NDIM + d2);
        float dp = warpSum(h.x * r.x + h.y * r.y);
        float c = -2.f * dp;
        ax = fmaf(we, fmaf(c, r.x, h.x), ax);
        ay = fmaf(we, fmaf(c, r.y, h.y), ay);
    }
    float2 o; o.x = tanhf(ax); o.y = tanhf(ay);
    *(float2*)(g_out + node * FEAT + col_out + d2) = o;
}

// ---------------- fused tail: logits+softmax, proxy feature, gate, blend ----------------
// smem (floats):
//   o_s   [192][PITCH]  outputs transposed   (o_s[d*P + n])
//   pf_s  [192][PITCH]  proxy_feature transposed
//   att_s [64][PITCH]   logits/softmax; later: per-chunk result stage
//   prx_s [64][192]     raw proxy; later per-chunk: 64 rows of gate_w
//   inv_s [64]          1/||o_n||
#define OS_OFF   0
#define PF_OFF   (FEAT * PITCH)
#define AT_OFF   (2 * FEAT * PITCH)
#define PRX_OFF  (2 * FEAT * PITCH + NPROXY * PITCH)
#define INV_OFF  (PRX_OFF + NPROXY * FEAT)
#define SM_FLOATS (INV_OFF + TTILE)
#define SM_BYTES  (SM_FLOATS * 4)

__global__ __launch_bounds__(FUSE_THREADS, 1) void fuse_kernel(
    const float* __restrict__ proxy, const float* __restrict__ gate_w,
    const float* __restrict__ gate_b, float* __restrict__ out, int N)
{
    extern __shared__ float sm[];
    float* o_s   = sm + OS_OFF;
    float* pf_s  = sm + PF_OFF;
    float* att_s = sm + AT_OFF;
    float* prx_s = sm + PRX_OFF;
    float* inv_s = sm + INV_OFF;

    const int tid = threadIdx.x;
    const int n0 = blockIdx.x * TTILE;

    // P0: load output tile transposed + raw proxy
    for (int idx = tid; idx < TTILE * FEAT; idx += FUSE_THREADS) {
        int n = idx / FEAT, d = idx - n * FEAT;
        float v = (n0 + n < N) ? g_out[(n0 + n) * FEAT + d] : 0.f;
        o_s[d * PITCH + n] = v;
    }
    for (int idx = tid; idx < NPROXY * FEAT; idx += FUSE_THREADS)
        prx_s[idx] = proxy[idx];
    __syncthreads();

    // P0b: per-node inverse norm
    if (tid < TTILE) {
        float ss = 0.f;
        #pragma unroll 4
        for (int d = 0; d < FEAT; d++) { float v = o_s[d * PITCH + tid]; ss += v * v; }
        inv_s[tid] = 1.f / fmaxf(sqrtf(ss), 1e-12f);
    }
    __syncthreads();

    const int p  = tid & 31;       // node pair index: nodes {2p, 2p+1}
    const int grp = tid >> 5;      // 0..15

    // P1: logits[j][n] = inv_o[n]*pinv[j]*(o_n . proxy_j)
    {
        const int jbase = grp * 4;
        float a0[4] = {0,0,0,0}, a1[4] = {0,0,0,0};
        for (int d = 0; d < FEAT; d += 2) {
            float2 A0 = *(const float2*)(o_s + d * PITCH + 2 * p);
            float2 A1 = *(const float2*)(o_s + (d + 1) * PITCH + 2 * p);
            #pragma unroll
            for (int jj = 0; jj < 4; jj++) {
                float2 pj = *(const float2*)(prx_s + (jbase + jj) * FEAT + d);
                a0[jj] = fmaf(A0.x, pj.x, fmaf(A1.x, pj.y, a0[jj]));
                a1[jj] = fmaf(A0.y, pj.x, fmaf(A1.y, pj.y, a1[jj]));
            }
        }
        float i0 = inv_s[2 * p], i1 = inv_s[2 * p + 1];
        #pragma unroll
        for (int jj = 0; jj < 4; jj++) {
            int j = jbase + jj;
            float pv = g_pinv[j];
            att_s[j * PITCH + 2 * p]     = a0[jj] * i0 * pv;
            att_s[j * PITCH + 2 * p + 1] = a1[jj] * i1 * pv;
        }
    }
    __syncthreads();

    // P1b: softmax over j (64) per node
    if (tid < TTILE) {
        int n = tid;
        float m = -3.0e38f;
        for (int j = 0; j < NPROXY; j++) m = fmaxf(m, att_s[j * PITCH + n]);
        float s = 0.f;
        for (int j = 0; j < NPROXY; j++) {
            float e = expf(att_s[j * PITCH + n] - m);
            att_s[j * PITCH + n] = e; s += e;
        }
        float is = 1.f / s;
        for (int j = 0; j < NPROXY; j++) att_s[j * PITCH + n] *= is;
    }
    __syncthreads();

    // P2: pf[d][n] = o[d][n] - sum_j att[j][n] * proxy[j][d]
    {
        const int d0 = grp * 12;
        float s0[12], s1[12];
        #pragma unroll
        for (int i = 0; i < 12; i++) { s0[i] = 0.f; s1[i] = 0.f; }
        for (int j = 0; j < NPROXY; j++) {
            float2 a = *(const float2*)(att_s + j * PITCH + 2 * p);
            const float* pr = prx_s + j * FEAT + d0;
            float4 q0 = *(const float4*)(pr);
            float4 q1 = *(const float4*)(pr + 4);
            float4 q2 = *(const float4*)(pr + 8);
            float pv[12] = {q0.x,q0.y,q0.z,q0.w,q1.x,q1.y,q1.z,q1.w,q2.x,q2.y,q2.z,q2.w};
            #pragma unroll
            for (int i = 0; i < 12; i++) {
                s0[i] = fmaf(a.x, pv[i], s0[i]);
                s1[i] = fmaf(a.y, pv[i], s1[i]);
            }
        }
        #pragma unroll
        for (int i = 0; i < 12; i++) {
            int d = d0 + i;
            float2 o2 = *(const float2*)(o_s + d * PITCH + 2 * p);
            float2 pf2; pf2.x = o2.x - s0[i]; pf2.y = o2.y - s1[i];
            *(float2*)(pf_s + d * PITCH + 2 * p) = pf2;
        }
    }

    // P3: gate GEMM (192x192) in 3 chunks of 64 rows; f32x2 node-pair packing
    for (int c = 0; c < 3; c++) {
        __syncthreads();  // att_s stage consumed / prx_s free
        for (int idx = tid; idx < 64 * FEAT; idx += FUSE_THREADS)
            prx_s[idx] = gate_w[c * 64 * FEAT + idx];
        __syncthreads();

        const int dl0 = grp * 4;   // local d within chunk: 4 rows per group
        ull acc[4] = {0, 0, 0, 0};
        for (int k = 0; k < FEAT; k += 4) {
            ull A0 = *(const ull*)(pf_s + (k    ) * PITCH + 2 * p);
            ull A1 = *(const ull*)(pf_s + (k + 1) * PITCH + 2 * p);
            ull A2 = *(const ull*)(pf_s + (k + 2) * PITCH + 2 * p);
            ull A3 = *(const ull*)(pf_s + (k + 3) * PITCH + 2 * p);
            #pragma unroll
            for (int i = 0; i < 4; i++) {
                float4 g = *(const float4*)(prx_s + (dl0 + i) * FEAT + k);
                acc[i] = ffma2(A0, pack2(g.x, g.x), acc[i]);
                acc[i] = ffma2(A1, pack2(g.y, g.y), acc[i]);
                acc[i] = ffma2(A2, pack2(g.z, g.z), acc[i]);
                acc[i] = ffma2(A3, pack2(g.w, g.w), acc[i]);
            }
        }
        #pragma unroll
        for (int i = 0; i < 4; i++) {
            int dl = dl0 + i, d = c * 64 + dl;
            float b = gate_b[d];
            float x0, x1; unpack2(acc[i], x0, x1);
            float2 o2  = *(const float2*)(o_s  + d * PITCH + 2 * p);
            float2 pf2 = *(const float2*)(pf_s + d * PITCH + 2 * p);
            float g0 = sigmoidf_(x0 + b), g1 = sigmoidf_(x1 + b);
            float r0 = pf2.x + g0 * (o2.x - pf2.x);
            float r1 = pf2.y + g1 * (o2.y - pf2.y);
            att_s[dl * PITCH + 2 * p]     = r0;   // stage for coalesced write
            att_s[dl * PITCH + 2 * p + 1] = r1;
        }
        __syncthreads();
        for (int idx = tid; idx < TTILE * 64; idx += FUSE_THREADS) {
            int n = idx >> 6, dl = idx & 63;
            if (n0 + n < N)
                out[(n0 + n) * FEAT + c * 64 + dl] = att_s[dl * PITCH + n];
        }
    }
}

// ---------------- launch ----------------
extern "C" void kernel_launch(void* const* d_in, const int* in_sizes, int n_in,
                              void* d_out, int out_size)
{
    const float* features = (const float*)d_in[0];
    const float* rel_emb  = (const float*)d_in[1];
    const float* proxy    = (const float*)d_in[2];
    const float* gate_w   = (const float*)d_in[3];
    const float* gate_b   = (const float*)d_in[4];
    const float* attn_k   = (const float*)d_in[5];
    const int*   adj      = (const int*)d_in[6];
    const int*   r_index  = (const int*)d_in[7];
    float*       out      = (float*)d_out;

    int N = in_sizes[0] / NDIM;
    int R = in_sizes[1] / NDIM;
    int E = in_sizes[6] / 2;
    int deg = E / N;
    int L = in_sizes[5] / NDIM;

    const int* src = adj + E;         // adj row 1 (cols = neighbor ids)
    const int* rid = r_index + E;     // r_index row 1 (relation ids)

    static bool attr_set = false;
    if (!attr_set) {
        cudaFuncSetAttribute(fuse_kernel,
                             cudaFuncAttributeMaxDynamicSharedMemorySize, SM_BYTES);
        attr_set = true;
    }

    prep_rel_kernel<<<R, NDIM>>>(rel_emb, attn_k, R, L);
    prep_proxy_kernel<<<NPROXY, FEAT>>>(proxy);
    tanh_kernel<<<(N * NDIM + 255) / 256, 256>>>(features, N);

    int lblocks = (N + 7) / 8;
    layer_kernel<<<lblocks, 256>>>(src, rid, 0, 0,       NDIM,     N, deg, R);
    layer_kernel<<<lblocks, 256>>>(src, rid, 1, NDIM,    2 * NDIM, N, deg, R);

    int fblocks = (N + TTILE - 1) / TTILE;
    fuse_kernel<<<fblocks, FUSE_THREADS, SM_BYTES>>>(proxy, gate_w, gate_b, out, N);
}

// round 5
// speedup vs baseline: 1.0467x; 1.0467x over previous
#include <cuda_runtime.h>
#include <math.h>

typedef unsigned long long ull;

#define FULLMASK 0xFFFFFFFFu
#define FEAT 192
#define NDIM 64
#define NPROXY 64
#define MAXN 50000
#define MAXR 512
#define PK 194          // pitch for K=192 arrays: half-pitch 97 odd -> conflict-free LDS.64
#define PJ 66           // pitch for J=64 arrays: half-pitch 33 odd

// ---------------- static scratch ----------------
static __device__ float g_out[MAXN * FEAT];     // concat outputs [N,192]
static __device__ float g_pf[MAXN * FEAT];      // proxy_feature scratch [N,192]
static __device__ float g_reln[MAXR * NDIM];    // normalized rel_emb rows
static __device__ float g_attrel[2 * MAXR];     // per-(layer,rel) attention scalar

// ---------------- helpers ----------------
__device__ __forceinline__ ull ffma2(ull a, ull b, ull c) {
    ull d;
    asm("fma.rn.f32x2 %0, %1, %2, %3;" : "=l"(d) : "l"(a), "l"(b), "l"(c));
    return d;
}
__device__ __forceinline__ void unpack2(ull v, float& lo, float& hi) {
    asm("mov.b64 {%0, %1}, %2;" : "=f"(lo), "=f"(hi) : "l"(v));
}
__device__ __forceinline__ float warpSum(float v) {
    #pragma unroll
    for (int o = 16; o; o >>= 1) v += __shfl_xor_sync(FULLMASK, v, o);
    return v;
}
__device__ __forceinline__ float sigmoidf_(float x) { return 1.f / (1.f + expf(-x)); }

// ---------------- prep: normalize rel rows + per-layer attention scalars ----------------
__global__ void prep_rel_kernel(const float* __restrict__ rel_emb,
                                const float* __restrict__ ak, int R, int L)
{
    __shared__ float red[2];
    int r = blockIdx.x, t = threadIdx.x;     // 64 threads
    float v = rel_emb[r * NDIM + t];
    float ss = warpSum(v * v);
    int w = t >> 5, ln = t & 31;
    if (ln == 0) red[w] = ss;
    __syncthreads();
    float inv = 1.f / fmaxf(sqrtf(red[0] + red[1]), 1e-12f);
    float vn = v * inv;
    g_reln[r * NDIM + t] = vn;
    for (int l = 0; l < L; l++) {
        __syncthreads();
        float a = warpSum(vn * ak[l * NDIM + t]);
        if (ln == 0) red[w] = a;
        __syncthreads();
        if (t == 0) g_attrel[l * R + r] = red[0] + red[1];
    }
}

// ---------------- tanh(features) -> outputs[:, 0:64] ----------------
__global__ void tanh_kernel(const float* __restrict__ feat, int N)
{
    int i = blockIdx.x * blockDim.x + threadIdx.x;
    if (i < N * (NDIM / 4)) {
        float4 v = ((const float4*)feat)[i];
        int n = i >> 4, d4 = (i & 15) * 4;
        float4 o;
        o.x = tanhf(v.x); o.y = tanhf(v.y); o.z = tanhf(v.z); o.w = tanhf(v.w);
        *(float4*)(g_out + n * FEAT + d4) = o;
    }
}

// ---------------- GNN layer: 2 nodes per warp, 16 lanes x 4 dims each ----------------
__global__ __launch_bounds__(256) void layer_kernel(
    const int* __restrict__ src, const int* __restrict__ rid,
    int l, int col_in, int col_out, int N, int deg, int R)
{
    __shared__ float4 ec[16][32];     // [node slot][edge] = {h_off, r_off, w, -}
    const int tid = threadIdx.x;
    const int warp = tid >> 5, lane = tid & 31;
    const int half = lane >> 4, hl = lane & 15;
    int node = blockIdx.x * 16 + warp * 2 + half;
    if (node >= N) node = N - 1;      // duplicate work, identical writes (safe)
    const int slot = warp * 2 + half;
    const float* __restrict__ attrel = g_attrel + l * R;
    const int e0 = node * deg;

    // softmax over deg edges using 16 lanes (<=2 edges per lane)
    int ea = hl, eb = hl + 16;
    bool va = ea < deg, vb = eb < deg;
    int sa = 0, ra = 0, sb = 0, rb = 0;
    float aa = -3.0e38f, ab = -3.0e38f;
    if (va) { sa = src[e0 + ea]; ra = rid[e0 + ea]; aa = attrel[ra]; }
    if (vb) { sb = src[e0 + eb]; rb = rid[e0 + eb]; ab = attrel[rb]; }
    float m = fmaxf(aa, ab);
    #pragma unroll
    for (int o = 8; o; o >>= 1) m = fmaxf(m, __shfl_xor_sync(FULLMASK, m, o));
    float xa = va ? expf(aa - m) : 0.f;
    float xb = vb ? expf(ab - m) : 0.f;
    float s = xa + xb;
    #pragma unroll
    for (int o = 8; o; o >>= 1) s += __shfl_xor_sync(FULLMASK, s, o);
    float is = 1.f / s;
    if (va) ec[slot][ea] = make_float4(__int_as_float(sa * FEAT + col_in),
                                       __int_as_float(ra * NDIM), xa * is, 0.f);
    if (vb) ec[slot][eb] = make_float4(__int_as_float(sb * FEAT + col_in),
                                       __int_as_float(rb * NDIM), xb * is, 0.f);
    __syncwarp();

    const int d4 = hl * 4;
    float4 acc = make_float4(0.f, 0.f, 0.f, 0.f);
    for (int e = 0; e < deg; e++) {
        float4 t = ec[slot][e];
        const float4 h = *(const float4*)(g_out + __float_as_int(t.x) + d4);
        const float4 r = *(const float4*)(g_reln + __float_as_int(t.y) + d4);
        float dp = fmaf(h.x, r.x, fmaf(h.y, r.y, fmaf(h.z, r.z, h.w * r.w)));
        #pragma unroll
        for (int o = 8; o; o >>= 1) dp += __shfl_xor_sync(FULLMASK, dp, o);
        float c = -2.f * dp;
        float w = t.z;
        acc.x = fmaf(w, fmaf(c, r.x, h.x), acc.x);
        acc.y = fmaf(w, fmaf(c, r.y, h.y), acc.y);
        acc.z = fmaf(w, fmaf(c, r.z, h.z), acc.z);
        acc.w = fmaf(w, fmaf(c, r.w, h.w), acc.w);
    }
    float4 o4;
    o4.x = tanhf(acc.x); o4.y = tanhf(acc.y);
    o4.z = tanhf(acc.z); o4.w = tanhf(acc.w);
    *(float4*)(g_out + node * FEAT + col_out + d4) = o4;
}

// ---------------- proxy kernel: logits + softmax + proxy_feature -> g_pf ----------------
// smem floats: o_s 64*PK | px_s 64*PK | pT_s 192*PJ | att_s 64*PJ | inv 64 | pinv 64
#define PA_OS    0
#define PA_PX    (64 * PK)
#define PA_PT    (128 * PK)
#define PA_ATT   (128 * PK + 192 * PJ)
#define PA_INV   (PA_ATT + 64 * PJ)
#define PA_PINV  (PA_INV + 64)
#define PA_FLOATS (PA_PINV + 64)
#define PA_BYTES (PA_FLOATS * 4)

__global__ __launch_bounds__(256, 1) void proxy_kernel(
    const float* __restrict__ proxy, int N)
{
    extern __shared__ float sm[];
    float* o_s   = sm + PA_OS;
    float* px_s  = sm + PA_PX;
    float* pT_s  = sm + PA_PT;
    float* att_s = sm + PA_ATT;
    float* inv_s = sm + PA_INV;
    float* pinv_s= sm + PA_PINV;
    const int tid = threadIdx.x;
    const int n0 = blockIdx.x * 64;

    for (int idx = tid; idx < 64 * 96; idx += 256) {
        int n = idx / 96, k2 = idx - n * 96;
        float2 v = make_float2(0.f, 0.f);
        if (n0 + n < N) v = *(const float2*)(g_out + (n0 + n) * FEAT + 2 * k2);
        *(float2*)(o_s + n * PK + 2 * k2) = v;
    }
    for (int idx = tid; idx < 64 * 96; idx += 256) {
        int j = idx / 96, k2 = idx - j * 96;
        float2 v = *(const float2*)(proxy + j * FEAT + 2 * k2);
        *(float2*)(px_s + j * PK + 2 * k2) = v;
        pT_s[(2 * k2) * PJ + j]     = v.x;
        pT_s[(2 * k2 + 1) * PJ + j] = v.y;
    }
    __syncthreads();

    // inverse norms (4 threads per row)
    {
        int n = tid >> 2, sub = tid & 3;
        float ss = 0.f;
        for (int d = sub; d < FEAT; d += 4) { float v = o_s[n * PK + d]; ss = fmaf(v, v, ss); }
        ss += __shfl_xor_sync(FULLMASK, ss, 1);
        ss += __shfl_xor_sync(FULLMASK, ss, 2);
        if (sub == 0) inv_s[n] = 1.f / fmaxf(sqrtf(ss), 1e-12f);
        float pp = 0.f;
        for (int d = sub; d < FEAT; d += 4) { float v = px_s[n * PK + d]; pp = fmaf(v, v, pp); }
        pp += __shfl_xor_sync(FULLMASK, pp, 1);
        pp += __shfl_xor_sync(FULLMASK, pp, 2);
        if (sub == 0) pinv_s[n] = 1.f / fmaxf(sqrtf(pp), 1e-12f);
    }
    __syncthreads();

    const int nq = tid & 15;
    const int rest = tid >> 4;   // 0..15

    // P1: logits (k-paired f32x2, I=4 nodes x J=4 proxies)
    {
        ull acc[4][4];
        #pragma unroll
        for (int i = 0; i < 4; i++)
            #pragma unroll
            for (int j = 0; j < 4; j++) acc[i][j] = 0ull;
        const float* ap = o_s + nq * PK;
        const float* bp = px_s + rest * 4 * PK;
        #pragma unroll 4
        for (int k = 0; k < FEAT; k += 2) {
            ull A[4], B[4];
            #pragma unroll
            for (int i = 0; i < 4; i++) A[i] = *(const ull*)(ap + i * 16 * PK + k);
            #pragma unroll
            for (int j = 0; j < 4; j++) B[j] = *(const ull*)(bp + j * PK + k);
            #pragma unroll
            for (int i = 0; i < 4; i++)
                #pragma unroll
                for (int j = 0; j < 4; j++) acc[i][j] = ffma2(A[i], B[j], acc[i][j]);
        }
        #pragma unroll
        for (int i = 0; i < 4; i++) {
            int n = nq + 16 * i;
            float in_ = inv_s[n];
            #pragma unroll
            for (int j = 0; j < 4; j++) {
                int jj = rest * 4 + j;
                float lo, hi; unpack2(acc[i][j], lo, hi);
                att_s[n * PJ + jj] = (lo + hi) * in_ * pinv_s[jj];
            }
        }
    }
    __syncthreads();

    // softmax over 64 proxies per node (4 threads per node)
    {
        int n = tid >> 2, sub = tid & 3;
        float vbuf[16];
        float m = -3.0e38f;
        #pragma unroll
        for (int t = 0; t < 16; t++) { vbuf[t] = att_s[n * PJ + sub + 4 * t]; m = fmaxf(m, vbuf[t]); }
        m = fmaxf(m, __shfl_xor_sync(FULLMASK, m, 1));
        m = fmaxf(m, __shfl_xor_sync(FULLMASK, m, 2));
        float s = 0.f;
        #pragma unroll
        for (int t = 0; t < 16; t++) { vbuf[t] = expf(vbuf[t] - m); s += vbuf[t]; }
        s += __shfl_xor_sync(FULLMASK, s, 1);
        s += __shfl_xor_sync(FULLMASK, s, 2);
        float is = 1.f / s;
        #pragma unroll
        for (int t = 0; t < 16; t++) att_s[n * PJ + sub + 4 * t] = vbuf[t] * is;
    }
    __syncthreads();

    // P2: pf = o - att @ proxy (j-paired, I=4 nodes x 6 dims, 2 dim-chunks of 96)
    for (int c2 = 0; c2 < 2; c2++) {
        ull acc[4][6];
        #pragma unroll
        for (int i = 0; i < 4; i++)
            #pragma unroll
            for (int mm = 0; mm < 6; mm++) acc[i][mm] = 0ull;
        const float* ap = att_s + nq * PJ;
        const float* bp = pT_s + (c2 * 96 + rest * 6) * PJ;
        #pragma unroll 2
        for (int j = 0; j < NPROXY; j += 2) {
            ull A[4], B[6];
            #pragma unroll
            for (int i = 0; i < 4; i++) A[i] = *(const ull*)(ap + i * 16 * PJ + j);
            #pragma unroll
            for (int mm = 0; mm < 6; mm++) B[mm] = *(const ull*)(bp + mm * PJ + j);
            #pragma unroll
            for (int i = 0; i < 4; i++)
                #pragma unroll
                for (int mm = 0; mm < 6; mm++) acc[i][mm] = ffma2(A[i], B[mm], acc[i][mm]);
        }
        #pragma unroll
        for (int i = 0; i < 4; i++) {
            int n = nq + 16 * i;
            bool ok = (n0 + n < N);
            #pragma unroll
            for (int mm = 0; mm < 6; mm++) {
                int d = c2 * 96 + rest * 6 + mm;
                float lo, hi; unpack2(acc[i][mm], lo, hi);
                float pf = o_s[n * PK + d] - (lo + hi);
                if (ok) g_pf[(n0 + n) * FEAT + d] = pf;
            }
        }
    }
}

// ---------------- gate kernel: sigmoid(pf @ W^T + b) blend (2 CTAs/SM) ----------------
// smem floats: pf_s 64*PK | gw_s 64*PK | gb_s 192
#define GB_PF 0
#define GB_GW (64 * PK)
#define GB_B  (128 * PK)
#define GB_FLOATS (GB_B + 192)
#define GB_BYTES (GB_FLOATS * 4)

__global__ __launch_bounds__(256, 2) void gate_kernel(
    const float* __restrict__ gate_w, const float* __restrict__ gate_b,
    float* __restrict__ out, int N)
{
    extern __shared__ float sm[];
    float* pf_s = sm + GB_PF;
    float* gw_s = sm + GB_GW;
    float* gb_s = sm + GB_B;
    const int tid = threadIdx.x;
    const int n0 = blockIdx.x * 64;

    for (int idx = tid; idx < 64 * 96; idx += 256) {
        int n = idx / 96, k2 = idx - n * 96;
        float2 v = make_float2(0.f, 0.f);
        if (n0 + n < N) v = *(const float2*)(g_pf + (n0 + n) * FEAT + 2 * k2);
        *(float2*)(pf_s + n * PK + 2 * k2) = v;
    }
    if (tid < FEAT) gb_s[tid] = gate_b[tid];

    const int nq = tid & 15;
    const int rest = tid >> 4;

    for (int c = 0; c < 3; c++) {
        __syncthreads();   // pf/gb ready (c=0); gw_s consumed (c>0)
        for (int idx = tid; idx < 64 * 96; idx += 256) {
            int r = idx / 96, k2 = idx - r * 96;
            *(float2*)(gw_s + r * PK + 2 * k2) =
                *(const float2*)(gate_w + (c * 64 + r) * FEAT + 2 * k2);
        }
        __syncthreads();

        ull acc[4][4];
        #pragma unroll
        for (int i = 0; i < 4; i++)
            #pragma unroll
            for (int j = 0; j < 4; j++) acc[i][j] = 0ull;
        const float* ap = pf_s + nq * PK;
        const float* bp = gw_s + rest * 4 * PK;
        #pragma unroll 4
        for (int k = 0; k < FEAT; k += 2) {
            ull A[4], B[4];
            #pragma unroll
            for (int i = 0; i < 4; i++) A[i] = *(const ull*)(ap + i * 16 * PK + k);
            #pragma unroll
            for (int j = 0; j < 4; j++) B[j] = *(const ull*)(bp + j * PK + k);
            #pragma unroll
            for (int i = 0; i < 4; i++)
                #pragma unroll
                for (int j = 0; j < 4; j++) acc[i][j] = ffma2(A[i], B[j], acc[i][j]);
        }
        #pragma unroll
        for (int i = 0; i < 4; i++) {
            int n = nq + 16 * i;
            bool ok = (n0 + n < N);
            #pragma unroll
            for (int j = 0; j < 4; j++) {
                int d = c * 64 + rest * 4 + j;
                float lo, hi; unpack2(acc[i][j], lo, hi);
                float g = sigmoidf_(lo + hi + gb_s[d]);
                float pf = pf_s[n * PK + d];
                if (ok) {
                    float o = g_out[(n0 + n) * FEAT + d];
                    out[(n0 + n) * FEAT + d] = pf + g * (o - pf);
                }
            }
        }
    }
}

// ---------------- launch ----------------
extern "C" void kernel_launch(void* const* d_in, const int* in_sizes, int n_in,
                              void* d_out, int out_size)
{
    const float* features = (const float*)d_in[0];
    const float* rel_emb  = (const float*)d_in[1];
    const float* proxy    = (const float*)d_in[2];
    const float* gate_w   = (const float*)d_in[3];
    const float* gate_b   = (const float*)d_in[4];
    const float* attn_k   = (const float*)d_in[5];
    const int*   adj      = (const int*)d_in[6];
    const int*   r_index  = (const int*)d_in[7];
    float*       out      = (float*)d_out;

    int N = in_sizes[0] / NDIM;
    int R = in_sizes[1] / NDIM;
    int E = in_sizes[6] / 2;
    int deg = E / N;
    int L = in_sizes[5] / NDIM;

    const int* src = adj + E;         // adj row 1: neighbor (col) ids
    const int* rid = r_index + E;     // r_index row 1: relation ids

    cudaFuncSetAttribute(proxy_kernel,
                         cudaFuncAttributeMaxDynamicSharedMemorySize, PA_BYTES);
    cudaFuncSetAttribute(gate_kernel,
                         cudaFuncAttributeMaxDynamicSharedMemorySize, GB_BYTES);

    prep_rel_kernel<<<R, NDIM>>>(rel_emb, attn_k, R, L);
    tanh_kernel<<<(N * (NDIM / 4) + 255) / 256, 256>>>(features, N);

    int lblocks = (N + 15) / 16;
    layer_kernel<<<lblocks, 256>>>(src, rid, 0, 0,    NDIM,     N, deg, R);
    layer_kernel<<<lblocks, 256>>>(src, rid, 1, NDIM, 2 * NDIM, N, deg, R);

    int tblocks = (N + 63) / 64;
    proxy_kernel<<<tblocks, 256, PA_BYTES>>>(proxy, N);
    gate_kernel<<<tblocks, 256, GB_BYTES>>>(gate_w, gate_b, out, N);
}